// round 1
// baseline (speedup 1.0000x reference)
#include <cuda_runtime.h>
#include <math.h>

#define BATCH   16
#define HEADS   16
#define DIM     128
#define BS      16        // cache block size
#define MAX_CTX 1024
#define NTBL    96        // block_tables width
#define PT_LEN  32        // prompt blocks to skip
#define QSCALE  0.08838834764831845f
#define CHUNK   128       // positions per partial CTA
#define NCHUNK  8
#define NEG_INF -1e30f

// scratch for split-context partials (allocation-free rule: __device__ globals)
__device__ float g_m[BATCH*HEADS*NCHUNK];
__device__ float g_l[BATCH*HEADS*NCHUNK];
__device__ float g_acc[BATCH*HEADS*NCHUNK*DIM];

__global__ void __launch_bounds__(128) attn_partial(
    const float* __restrict__ q,
    const float* __restrict__ k_new,
    const float* __restrict__ v_new,
    const float* __restrict__ kc,
    const float* __restrict__ vc,
    const int*   __restrict__ btab,
    const int*   __restrict__ ctx_lens,
    const float* __restrict__ bias)
{
    const int chunk = blockIdx.x;
    const int h     = blockIdx.y;
    const int b     = blockIdx.z;
    const int ctx   = ctx_lens[b];
    const int start = chunk * CHUNK;
    if (start >= ctx) return;

    const int t    = threadIdx.x;   // 0..127
    const int wid  = t >> 5;
    const int lane = t & 31;

    __shared__ float sh_s[BS];
    __shared__ float sh_p[BS];

    // per-lane q float4 (covers d = 4*lane .. 4*lane+3), pre-scaled
    const float4* qv = (const float4*)(q + (size_t)(b*HEADS + h)*DIM);
    float4 q4 = qv[lane];
    q4.x *= QSCALE; q4.y *= QSCALE; q4.z *= QSCALE; q4.w *= QSCALE;

    const int last = ctx - 1;   // position where k_new/v_new substitute the cache

    float m = NEG_INF, l = 0.f, acc = 0.f;

    for (int w = 0; w < CHUNK / BS; ++w) {
        const int kb      = chunk * (CHUNK / BS) + w;   // decode-region block idx
        const int posbase = kb * BS;
        if (posbase >= ctx) break;
        const int blk = btab[b*NTBL + PT_LEN + kb];
        const float* kblock = kc + ((size_t)blk*HEADS + h) * BS * DIM;

        // ---- scores: each warp handles 4 of the 16 positions ----
        #pragma unroll
        for (int i = 0; i < 4; ++i) {
            const int off = wid + 4*i;
            const int pos = posbase + off;
            const float4* kp = (pos == last)
                ? (const float4*)(k_new + (size_t)(b*HEADS + h)*DIM)
                : (const float4*)(kblock + off*DIM);
            const float4 k4 = kp[lane];
            float s = q4.x*k4.x + q4.y*k4.y + q4.z*k4.z + q4.w*k4.w;
            #pragma unroll
            for (int o = 16; o > 0; o >>= 1)
                s += __shfl_xor_sync(0xffffffffu, s, o);
            if (lane == 0) {
                if (pos < ctx) s += bias[((size_t)(b*HEADS + h))*MAX_CTX + pos];
                else           s  = NEG_INF;
                sh_s[off] = s;
            }
        }
        __syncthreads();

        // ---- online softmax update ----
        float bm = NEG_INF;
        #pragma unroll
        for (int k = 0; k < BS; ++k) bm = fmaxf(bm, sh_s[k]);
        const float m_new = fmaxf(m, bm);
        const float corr  = __expf(m - m_new);
        if (t < BS) sh_p[t] = __expf(sh_s[t] - m_new);
        __syncthreads();

        float psum = 0.f;
        #pragma unroll
        for (int k = 0; k < BS; ++k) psum += sh_p[k];
        l = l * corr + psum;

        // ---- V accumulate: thread t owns output dim t ----
        const float4* vp = (const float4*)(vc + (((size_t)blk*HEADS + h)*DIM + t) * BS);
        const float4 v0 = vp[0], v1 = vp[1], v2 = vp[2], v3 = vp[3];
        float vv[BS] = {v0.x,v0.y,v0.z,v0.w, v1.x,v1.y,v1.z,v1.w,
                        v2.x,v2.y,v2.z,v2.w, v3.x,v3.y,v3.z,v3.w};
        if (last >= posbase && last < posbase + BS)
            vv[last - posbase] = v_new[(size_t)(b*HEADS + h)*DIM + t];

        float a = 0.f;
        #pragma unroll
        for (int k = 0; k < BS; ++k) a += sh_p[k] * vv[k];
        acc = acc * corr + a;
        m = m_new;
        __syncthreads();   // protect sh_s/sh_p before next block iter
    }

    const int idx = (b*HEADS + h)*NCHUNK + chunk;
    if (t == 0) { g_m[idx] = m; g_l[idx] = l; }
    g_acc[(size_t)idx*DIM + t] = acc;
}

__global__ void __launch_bounds__(128) attn_reduce(
    const int* __restrict__ ctx_lens,
    float*     __restrict__ out)
{
    const int h = blockIdx.x;
    const int b = blockIdx.y;
    const int t = threadIdx.x;                // output dim
    const int ctx  = ctx_lens[b];
    const int nch  = (ctx + CHUNK - 1) / CHUNK;
    const int base = (b*HEADS + h)*NCHUNK;

    float M = NEG_INF;
    for (int c = 0; c < nch; ++c) M = fmaxf(M, g_m[base + c]);
    float L = 0.f, o = 0.f;
    for (int c = 0; c < nch; ++c) {
        const float wgt = __expf(g_m[base + c] - M);
        L += g_l[base + c] * wgt;
        o += g_acc[(size_t)(base + c)*DIM + t] * wgt;
    }
    out[(size_t)(b*HEADS + h)*DIM + t] = o / L;
}

extern "C" void kernel_launch(void* const* d_in, const int* in_sizes, int n_in,
                              void* d_out, int out_size)
{
    const float* q     = (const float*)d_in[0];
    const float* k_new = (const float*)d_in[1];
    const float* v_new = (const float*)d_in[2];
    const float* kc    = (const float*)d_in[3];
    const float* vc    = (const float*)d_in[4];
    // d_in[5] = slot_mapping (unused: substitution at pos==ctx-1 reproduces the scatter)
    const int*   btab  = (const int*)d_in[6];
    const int*   ctx   = (const int*)d_in[7];
    const float* bias  = (const float*)d_in[8];
    // d_in[9] = max_prompt_len (constant 512 -> PT_LEN=32 baked in)

    dim3 g1(NCHUNK, HEADS, BATCH);
    attn_partial<<<g1, 128>>>(q, k_new, v_new, kc, vc, btab, ctx, bias);
    dim3 g2(HEADS, BATCH);
    attn_reduce<<<g2, 128>>>(ctx, (float*)d_out);
}